// round 10
// baseline (speedup 1.0000x reference)
#include <cuda_runtime.h>

// ---------------------------------------------------------------------------
// EquivariantAttention — fp32 persistent kernel, 1 block/SM, 1024 threads.
// Two nodes processed per iteration: each 512-thread half runs the full
// per-node phase pipeline on its own node (smem working set per half).
// Software-pipelined global loads (idx -> gather, ef, bases, f) per half.
// ---------------------------------------------------------------------------

namespace {

constexpr int NODES = 20000;
constexpr int NBR   = 16;
constexpr int MULT  = 8;
constexpr int DIMV  = 4;
constexpr int EDIM  = 32;
constexpr int HIDN  = 64;
constexpr int FLAT  = 256;   // (NL*MULT)^2
constexpr float ATT_SCALE = 0.35355339059327373f;   // 8^-0.5

struct alignas(16) SmemT {
    // weights (loaded once per block, shared by both halves)
    float w2s[2][HIDN * FLAT];   // repacked swizzled layout (see pos calc)
    float w1s[2][EDIM * HIDN];   // [br][i*64 + c]
    float b1s[2][HIDN];
    float b2s[2][FLAT];
    float qw[16 * 8];
    float ow[16 * 8];
    float qb[8];
    float ob[8];
    // per-half, per-node input set (double-buffered for prefetch)
    float ef[2][2][16][32];      // [half][buf]
    float fsrc[2][2][16][32];
    float fnode[2][2][32];
    float bas1[2][2][2][16][8];  // [half][buf][br][e][d*2+l]
    float bas2[2][2][2][16][8];  // [half][buf][br][e][l*4+d]
    // per-half intermediates (single-buffered)
    float hbuf[2][2][16][HIDN];  // [half][br]
    float tmpb[2][2][16][16];    // [half][br][e][m*2+l]
    float t2b[2][2][16][16];     // [half][br][e][o*2+l]
    float kvb[2][2][16][32];     // [half][br][e][m*4+d]
    float qvec[2][32];
    float attn[2][4][16];
    float ao[2][32];
};

} // namespace

__global__ __launch_bounds__(1024, 1)
void eqattn_kernel(
    const float* __restrict__ bk1, const float* __restrict__ bk2,
    const float* __restrict__ bv1, const float* __restrict__ bv2,
    const float* __restrict__ efeat, const float* __restrict__ fin,
    const float* __restrict__ q_w,  const float* __restrict__ q_b,
    const float* __restrict__ k_w1, const float* __restrict__ k_b1,
    const float* __restrict__ k_w2, const float* __restrict__ k_b2,
    const float* __restrict__ v_w1, const float* __restrict__ v_b1,
    const float* __restrict__ v_w2, const float* __restrict__ v_b2,
    const float* __restrict__ o_w,  const float* __restrict__ o_b,
    const int*   __restrict__ nidx32,
    float* __restrict__ out)
{
    extern __shared__ unsigned char smem_raw[];
    SmemT& S = *reinterpret_cast<SmemT*>(smem_raw);
    const int tid  = threadIdx.x;
    const int half = tid >> 9;        // which node of the pair
    const int t    = tid & 511;       // thread id within the half

    // int64 vs int32 neighbor_idx sniff (little-endian high words are 0)
    const bool is64 = (nidx32[1] == 0 && nidx32[3] == 0 &&
                       nidx32[5] == 0 && nidx32[7] == 0);
    const long long* nidx64 = reinterpret_cast<const long long*>(nidx32);

    // ---------------- prologue: stage all weights into smem ----------------
    // w2 repack: value (c, p) with p = i*16 + jh*8 + jq*2 + r.
    // lane_r = (i&7)*2 + jh. Stored at pos = (i>>3)*128 + jq*32 + lane_r*2 + r
    // so a 16-lane group's float2 reads per (c, jq) are 128B contiguous.
    for (int w = tid; w < 2 * HIDN * FLAT; w += 1024) {
        int br  = w >> 14;
        int rem = w & 16383;           // c*256 + p
        int p   = rem & 255;
        const float* g = br ? v_w2 : k_w2;
        float val = g[rem];
        int i  = p >> 4;
        int jh = (p >> 3) & 1;
        int jq = (p >> 1) & 3;
        int r  = p & 1;
        int pos = ((i >> 3) << 7) + (jq << 5) + ((((i & 7) << 1) | jh) << 1) + r;
        S.w2s[br][(rem & ~255) + pos] = val;
    }
    for (int w = tid; w < 2 * EDIM * HIDN; w += 1024) {
        int br = w >> 11;
        int rem = w & 2047;
        S.w1s[br][rem] = (br ? v_w1 : k_w1)[rem];
    }
    if (tid < 512) {
        int br = tid >> 8, p = tid & 255;
        S.b2s[br][p] = (br ? v_b2 : k_b2)[p];
    }
    if (tid < 128) {
        int br = tid >> 6;
        S.b1s[br][tid & 63] = (br ? v_b1 : k_b1)[tid & 63];
        S.qw[tid] = q_w[tid];
        S.ow[tid] = o_w[tid];
    }
    if (tid < 8) { S.qb[tid] = q_b[tid]; S.ob[tid] = o_b[tid]; }

    // prefetch thread roles (within half)
    const int pe   = t >> 5, pi = t & 31;         // ef / fsrc element
    const int parr = t >> 7;                      // which basis array
    const int peb  = (t >> 3) & 15, px = t & 7;   // basis element

    const int stride = 2 * (int)gridDim.x;

    // ------------- prologue: load first node's inputs into buffer 0 --------
    {
        const int n0 = 2 * (int)blockIdx.x + half;   // always < NODES
        int ib = n0 * NBR + pe;
        int iv = is64 ? (int)nidx64[ib] : nidx32[ib];
        S.ef[half][0][pe][pi]   = efeat[n0 * (NBR * EDIM) + t];
        S.fsrc[half][0][pe][pi] = fin[iv * (MULT * DIMV) + pi];
        const float* psrc = (parr == 0) ? bk1 : (parr == 1) ? bk2
                          : (parr == 2) ? bv1 : bv2;
        float bv = psrc[n0 * (NBR * 8) + peb * 8 + px];
        if (parr == 0)      S.bas1[half][0][0][peb][px] = bv;
        else if (parr == 1) S.bas2[half][0][0][peb][px] = bv;
        else if (parr == 2) S.bas1[half][0][1][peb][px] = bv;
        else                S.bas2[half][0][1][peb][px] = bv;
        if (t < 32) S.fnode[half][0][t] = fin[n0 * (MULT * DIMV) + t];
    }
    __syncthreads();

    // layer2 thread geometry (within half; half boundary is warp-aligned)
    const int warp  = t >> 5;
    const int lane  = t & 31;
    const int brw   = warp >> 3;         // branch for layer2 (0=k,1=v)
    const int wb    = warp & 7;
    const int eg2   = wb >> 1;           // edges eg2 + {0,4,8,12}
    const int ihalf = wb & 1;
    const int chalf = lane >> 4;         // 0/1: which half of c in [0,64)
    const int low4  = lane & 15;         // == (irow&7)*2 + jh  (matches repack)
    const int jh    = low4 & 1;
    const int irow  = (ihalf << 3) + (low4 >> 1);   // i in 0..15

    // ---------------------------- node loop --------------------------------
    // NODES is even and stride is even, so both halves always have a valid
    // node and identical trip counts (barrier-safe).
    int pb = 0;
    for (int n = 2 * (int)blockIdx.x + half; n < NODES; n += stride, pb ^= 1) {

        // ---- issue next node's global loads (consumed at end of iteration)
        const int n2 = n + stride;
        const bool pf = (n2 < NODES);
        float pf_ef = 0.0f, pf_fs = 0.0f, pf_bas = 0.0f, pf_fn = 0.0f;
        if (pf) {
            int ib = n2 * NBR + pe;
            int iv = is64 ? (int)nidx64[ib] : nidx32[ib];
            pf_ef = efeat[n2 * (NBR * EDIM) + t];
            pf_fs = fin[iv * (MULT * DIMV) + pi];
            const float* psrc = (parr == 0) ? bk1 : (parr == 1) ? bk2
                              : (parr == 2) ? bv1 : bv2;
            pf_bas = psrc[n2 * (NBR * 8) + peb * 8 + px];
            if (t < 32) pf_fn = fin[n2 * (MULT * DIMV) + t];
        }

        // phase 2: layer1 (h = gelu(ef@w1+b1)), tmp (f_src x bas1), q
        {
            const int br  = t >> 8;
            const int rem = t & 255;
            const int c   = rem & 63;
            const int eg  = rem >> 6;        // 0..3, edges eg+4k
            float acc0, acc1, acc2, acc3;
            acc0 = acc1 = acc2 = acc3 = S.b1s[br][c];
            #pragma unroll
            for (int i4 = 0; i4 < EDIM; i4 += 4) {
                float wa = S.w1s[br][(i4 + 0) * HIDN + c];
                float wbv = S.w1s[br][(i4 + 1) * HIDN + c];
                float wc = S.w1s[br][(i4 + 2) * HIDN + c];
                float wd = S.w1s[br][(i4 + 3) * HIDN + c];
                float4 e0 = *reinterpret_cast<const float4*>(&S.ef[half][pb][eg +  0][i4]);
                float4 e1 = *reinterpret_cast<const float4*>(&S.ef[half][pb][eg +  4][i4]);
                float4 e2 = *reinterpret_cast<const float4*>(&S.ef[half][pb][eg +  8][i4]);
                float4 e3 = *reinterpret_cast<const float4*>(&S.ef[half][pb][eg + 12][i4]);
                acc0 = fmaf(e0.x, wa, acc0); acc0 = fmaf(e0.y, wbv, acc0);
                acc0 = fmaf(e0.z, wc, acc0); acc0 = fmaf(e0.w, wd, acc0);
                acc1 = fmaf(e1.x, wa, acc1); acc1 = fmaf(e1.y, wbv, acc1);
                acc1 = fmaf(e1.z, wc, acc1); acc1 = fmaf(e1.w, wd, acc1);
                acc2 = fmaf(e2.x, wa, acc2); acc2 = fmaf(e2.y, wbv, acc2);
                acc2 = fmaf(e2.z, wc, acc2); acc2 = fmaf(e2.w, wd, acc2);
                acc3 = fmaf(e3.x, wa, acc3); acc3 = fmaf(e3.y, wbv, acc3);
                acc3 = fmaf(e3.z, wc, acc3); acc3 = fmaf(e3.w, wd, acc3);
            }
            // exact gelu: x * Phi(x)
            S.hbuf[half][br][eg +  0][c] = acc0 * normcdff(acc0);
            S.hbuf[half][br][eg +  4][c] = acc1 * normcdff(acc1);
            S.hbuf[half][br][eg +  8][c] = acc2 * normcdff(acc2);
            S.hbuf[half][br][eg + 12][c] = acc3 * normcdff(acc3);
        }
        {
            const int br = t >> 8;
            const int rem = t & 255;
            const int e = rem >> 4;
            const int j = rem & 15;          // m*2 + l
            const int m = j >> 1, l = j & 1;
            const float* fr = S.fsrc[half][pb][e];
            const float* b  = S.bas1[half][pb][br][e];
            float tt = fr[m * 4 + 0] * b[0 * 2 + l];
            tt = fmaf(fr[m * 4 + 1], b[1 * 2 + l], tt);
            tt = fmaf(fr[m * 4 + 2], b[2 * 2 + l], tt);
            tt = fmaf(fr[m * 4 + 3], b[3 * 2 + l], tt);
            S.tmpb[half][br][e][j] = tt;
        }
        if (t < 32) {
            const int m = t >> 2, d = t & 3;
            const int l = (d == 0) ? 0 : 1;
            float a = (d == 0) ? S.qb[m] : 0.0f;
            #pragma unroll
            for (int mp = 0; mp < MULT; mp++)
                a = fmaf(S.qw[(l * MULT + m) * MULT + mp],
                         S.fnode[half][pb][mp * 4 + d], a);
            S.qvec[half][t] = a;
        }
        __syncthreads();

        // phase 3: layer2 — rw = h@w2 + b2 (c-reduction split across half-warps),
        // then t2 = rw@tmp with shfl folds over (chalf, jh).
        {
            float rw[4][8];
            {
                const int p0 = (irow << 4) + (jh << 3);
                #pragma unroll
                for (int j = 0; j < 8; j++) {
                    // bias seeded only in the chalf==0 partial sum
                    float bb = (chalf == 0) ? S.b2s[brw][p0 + j] : 0.0f;
                    rw[0][j] = bb; rw[1][j] = bb; rw[2][j] = bb; rw[3][j] = bb;
                }
            }
            const float2* w2base =
                reinterpret_cast<const float2*>(&S.w2s[brw][(ihalf << 7) + (low4 << 1)]);
            const float* h0p = S.hbuf[half][brw][eg2 +  0];
            const float* h1p = S.hbuf[half][brw][eg2 +  4];
            const float* h2p = S.hbuf[half][brw][eg2 +  8];
            const float* h3p = S.hbuf[half][brw][eg2 + 12];
            const int c0 = chalf << 5;
            #pragma unroll 4
            for (int cc = 0; cc < 32; cc++) {
                const int c = c0 + cc;
                float hv0 = h0p[c], hv1 = h1p[c], hv2 = h2p[c], hv3 = h3p[c];
                const float2* wc = w2base + c * 128;   // +c*256 floats
                #pragma unroll
                for (int jq = 0; jq < 4; jq++) {
                    float2 w = wc[jq * 16];            // +jq*32 floats
                    rw[0][2 * jq]     = fmaf(hv0, w.x, rw[0][2 * jq]);
                    rw[0][2 * jq + 1] = fmaf(hv0, w.y, rw[0][2 * jq + 1]);
                    rw[1][2 * jq]     = fmaf(hv1, w.x, rw[1][2 * jq]);
                    rw[1][2 * jq + 1] = fmaf(hv1, w.y, rw[1][2 * jq + 1]);
                    rw[2][2 * jq]     = fmaf(hv2, w.x, rw[2][2 * jq]);
                    rw[2][2 * jq + 1] = fmaf(hv2, w.y, rw[2][2 * jq + 1]);
                    rw[3][2 * jq]     = fmaf(hv3, w.x, rw[3][2 * jq]);
                    rw[3][2 * jq + 1] = fmaf(hv3, w.y, rw[3][2 * jq + 1]);
                }
            }
            #pragma unroll
            for (int k = 0; k < 4; k++) {
                const int e = eg2 + 4 * k;
                const float* tp = &S.tmpb[half][brw][e][jh << 3];
                float acc = 0.0f;
                #pragma unroll
                for (int j = 0; j < 8; j++) acc = fmaf(rw[k][j], tp[j], acc);
                acc += __shfl_xor_sync(0xffffffffu, acc, 16);  // fold c-halves
                acc += __shfl_xor_sync(0xffffffffu, acc, 1);   // fold j-halves
                if ((lane & 17) == 0) S.t2b[half][brw][e][irow] = acc;
            }
        }
        __syncthreads();

        // phase 4: k/v = t2 x bas2   (1024 items per half, 2/thread)
        #pragma unroll
        for (int rep = 0; rep < 2; rep++) {
            int it = t + rep * 512;
            int br = it >> 9;
            int rem = it & 511;
            int e = rem >> 5;
            int p = rem & 31;                // o*4 + d
            int o = p >> 2, d = p & 3;
            float v = S.t2b[half][br][e][o * 2 + 0] * S.bas2[half][pb][br][e][0 * 4 + d];
            v = fmaf(S.t2b[half][br][e][o * 2 + 1], S.bas2[half][pb][br][e][1 * 4 + d], v);
            S.kvb[half][br][e][p] = v;
        }
        __syncthreads();

        // phase 5: logits + softmax (64 threads per half; 16-lane groups)
        if (t < 64) {
            const int h = t >> 4, kk = t & 15;
            float acc = 0.0f;
            #pragma unroll
            for (int dd = 0; dd < 8; dd++)
                acc = fmaf(S.qvec[half][h * 8 + dd], S.kvb[half][0][kk][h * 8 + dd], acc);
            acc *= ATT_SCALE;
            float mx = acc;
            #pragma unroll
            for (int o = 8; o >= 1; o >>= 1)
                mx = fmaxf(mx, __shfl_xor_sync(0xffffffffu, mx, o));
            float ex = expf(acc - mx);
            float sm = ex;
            #pragma unroll
            for (int o = 8; o >= 1; o >>= 1)
                sm += __shfl_xor_sync(0xffffffffu, sm, o);
            S.attn[half][h][kk] = ex / sm;
        }
        __syncthreads();

        // phase 6: attention output (32 threads per half)
        if (t < 32) {
            const int h = t >> 3;
            float acc = 0.0f;
            #pragma unroll
            for (int kk = 0; kk < NBR; kk++)
                acc = fmaf(S.attn[half][h][kk], S.kvb[half][1][kk][t], acc);
            S.ao[half][t] = acc;
        }
        __syncthreads();

        // phase 7: final eq_linear -> global
        if (t < 32) {
            const int m = t >> 2, d = t & 3;
            const int l = (d == 0) ? 0 : 1;
            float a = (d == 0) ? S.ob[m] : 0.0f;
            #pragma unroll
            for (int mp = 0; mp < MULT; mp++)
                a = fmaf(S.ow[(l * MULT + m) * MULT + mp], S.ao[half][mp * 4 + d], a);
            out[n * 32 + t] = a;
        }

        // ---- commit next node's inputs into the other buffer, then publish
        if (pf) {
            const int nb = pb ^ 1;
            S.ef[half][nb][pe][pi]   = pf_ef;
            S.fsrc[half][nb][pe][pi] = pf_fs;
            if (parr == 0)      S.bas1[half][nb][0][peb][px] = pf_bas;
            else if (parr == 1) S.bas2[half][nb][0][peb][px] = pf_bas;
            else if (parr == 2) S.bas1[half][nb][1][peb][px] = pf_bas;
            else                S.bas2[half][nb][1][peb][px] = pf_bas;
            if (t < 32) S.fnode[half][nb][t] = pf_fn;
        }
        __syncthreads();
    }
}

extern "C" void kernel_launch(void* const* d_in, const int* in_sizes, int n_in,
                              void* d_out, int out_size) {
    const float* bk1  = (const float*)d_in[0];
    const float* bk2  = (const float*)d_in[1];
    const float* bv1  = (const float*)d_in[2];
    const float* bv2  = (const float*)d_in[3];
    const float* ef   = (const float*)d_in[4];
    const float* fin  = (const float*)d_in[5];
    const float* q_w  = (const float*)d_in[6];
    const float* q_b  = (const float*)d_in[7];
    const float* k_w1 = (const float*)d_in[8];
    const float* k_b1 = (const float*)d_in[9];
    const float* k_w2 = (const float*)d_in[10];
    const float* k_b2 = (const float*)d_in[11];
    const float* v_w1 = (const float*)d_in[12];
    const float* v_b1 = (const float*)d_in[13];
    const float* v_w2 = (const float*)d_in[14];
    const float* v_b2 = (const float*)d_in[15];
    const float* o_w  = (const float*)d_in[16];
    const float* o_b  = (const float*)d_in[17];
    const int*   nidx = (const int*)d_in[18];
    float* out = (float*)d_out;

    int sms = 148;
    cudaDeviceGetAttribute(&sms, cudaDevAttrMultiProcessorCount, 0);
    if (sms <= 0) sms = 148;

    const int smem = (int)sizeof(SmemT);
    cudaFuncSetAttribute(eqattn_kernel,
                         cudaFuncAttributeMaxDynamicSharedMemorySize, smem);

    eqattn_kernel<<<sms, 1024, smem>>>(
        bk1, bk2, bv1, bv2, ef, fin,
        q_w, q_b, k_w1, k_b1, k_w2, k_b2,
        v_w1, v_b1, v_w2, v_b2, o_w, o_b,
        nidx, out);
}